// round 15
// baseline (speedup 1.0000x reference)
#include <cuda_runtime.h>
#include <cuda_bf16.h>
#include <cstdint>
#include <math.h>

#define NN 4096
#define BB 32
#define FF 66
#define UU 64
#define MM 5
#define FB 2112          // FF*BB
#define FBQ 264          // FB/8 uint4 (8 bf16) per row
#define NNZ_MAX 128
#define CH 1024          // pipeline chunk rows
#define PNB 16           // proj n-blocks per chunk (CH/64)

// ---------------- scratch ----------------
__device__ uint4 g_X0b[(size_t)NN * FBQ];
__device__ uint4 g_X2b[(size_t)NN * FBQ];
__device__ uint4 g_Mb[4][(size_t)NN * FBQ];   // [0]=S0@X, [1]=cheb(S0), [2]=S1@X, [3]=cheb(S1)
__device__ float g_U[(size_t)BB * NN * UU];
__device__ int2  g_sp[2][(size_t)NNZ_MAX * NN];  // packed {col_idx, val_bits}
__device__ int   g_cnt[2][NN];

// ---------------- packed f32x2 helpers ----------------
__device__ __forceinline__ unsigned long long pack2(float lo, float hi) {
    unsigned long long r;
    asm("mov.b64 %0, {%1, %2};" : "=l"(r) : "f"(lo), "f"(hi));
    return r;
}
__device__ __forceinline__ void unpack2(unsigned long long v, float& lo, float& hi) {
    asm("mov.b64 {%0, %1}, %2;" : "=f"(lo), "=f"(hi) : "l"(v));
}
__device__ __forceinline__ void ffma2(unsigned long long& d, unsigned long long a,
                                      unsigned long long b) {
    asm("fma.rn.f32x2 %0, %1, %2, %0;" : "+l"(d) : "l"(a), "l"(b));
}
// bf16x2 (one u32) -> packed f32x2 (u64); bf16->f32 is an exact 16-bit shift.
__device__ __forceinline__ unsigned long long bf2_to_f32x2(unsigned p) {
    unsigned long long r;
    asm("{ .reg .b32 lo, hi;\n\t"
        "prmt.b32 lo, %1, 0, 0x1044;\n\t"
        "prmt.b32 hi, %1, 0, 0x3244;\n\t"
        "mov.b64 %0, {lo, hi}; }" : "=l"(r) : "r"(p));
    return r;
}

// ---------------- sparse build (packed pairs) ----------------
__global__ void build_sparse_k(const float* __restrict__ S, int sup) {
    int gw   = (blockIdx.x * blockDim.x + threadIdx.x) >> 5;
    int lane = threadIdx.x & 31;
    if (gw >= NN) return;
    const float* row = S + (size_t)gw * NN;
    int2* sp = g_sp[sup];
    int c = 0;
    for (int j0 = 0; j0 < NN; j0 += 32) {
        float v = row[j0 + lane];
        unsigned m = __ballot_sync(0xffffffffu, v != 0.0f);
        int pre = __popc(m & ((1u << lane) - 1u));
        if (v != 0.0f) {
            int slot = c + pre;
            if (slot < NNZ_MAX)
                sp[(size_t)slot * NN + gw] = make_int2(j0 + lane, __float_as_int(v));
        }
        c += __popc(m);
    }
    if (lane == 0) g_cnt[sup][gw] = (c < NNZ_MAX) ? c : NNZ_MAX;
}

// ---------------- build X0 / static X2 (bf16) ----------------
__global__ void build_x_k(const float* __restrict__ inp, const float* __restrict__ hx) {
    int e = blockIdx.x * blockDim.x + threadIdx.x;
    if (e >= NN * FB) return;
    int n = e / FB;
    int rem = e - n * FB;
    int b = rem / FF;
    int f = rem - b * FF;
    __nv_bfloat16* X0 = (__nv_bfloat16*)g_X0b;
    __nv_bfloat16* X2 = (__nv_bfloat16*)g_X2b;
    float v;
    if (f < 2) {
        v = inp[(size_t)b * (NN * 2) + n * 2 + f];
        X2[e] = __float2bfloat16(v);
    } else {
        v = hx[(size_t)b * (NN * UU) + (size_t)n * UU + (f - 2)];
    }
    X0[e] = __float2bfloat16(v);
}

__device__ __forceinline__ uint4* x_buf(int s) { return s ? g_X2b : g_X0b; }

// ---------------- SpMM bodies (R14 math, bit-identical) ----------------
__device__ __forceinline__ void fma8p(unsigned long long* acc, uint4 x,
                                      unsigned long long v2) {
    const unsigned* p = (const unsigned*)&x;
#pragma unroll
    for (int q = 0; q < 4; q++)
        ffma2(acc[q], v2, bf2_to_f32x2(p[q]));
}

__device__ __forceinline__ void spmm_body(int sup, int i, int phase, int xsel) {
    int t = threadIdx.x;  // 0..263: one uint4 (8 bf16) = full row coverage
    const uint4* __restrict__ Xin = phase ? g_Mb[2 * sup] : x_buf(xsel);
    uint4* __restrict__ Yout = g_Mb[2 * sup + phase];
    const int2* __restrict__ sp = g_sp[sup];
    int cnt = g_cnt[sup][i];
    float alpha = phase ? 2.0f : 1.0f;

    unsigned long long acc[4];
#pragma unroll
    for (int q = 0; q < 4; q++) acc[q] = 0ULL;

    int k = 0;
    for (; k + 3 < cnt; k += 4) {
        int2 p0 = __ldg(&sp[(size_t)(k + 0) * NN + i]);
        int2 p1 = __ldg(&sp[(size_t)(k + 1) * NN + i]);
        int2 p2 = __ldg(&sp[(size_t)(k + 2) * NN + i]);
        int2 p3 = __ldg(&sp[(size_t)(k + 3) * NN + i]);
        uint4 x0 = __ldg(&Xin[(size_t)p0.x * FBQ + t]);
        uint4 x1 = __ldg(&Xin[(size_t)p1.x * FBQ + t]);
        uint4 x2 = __ldg(&Xin[(size_t)p2.x * FBQ + t]);
        uint4 x3 = __ldg(&Xin[(size_t)p3.x * FBQ + t]);
        float v0 = __int_as_float(p0.y), v1 = __int_as_float(p1.y);
        float v2 = __int_as_float(p2.y), v3 = __int_as_float(p3.y);
        fma8p(acc, x0, pack2(v0, v0));
        fma8p(acc, x1, pack2(v1, v1));
        fma8p(acc, x2, pack2(v2, v2));
        fma8p(acc, x3, pack2(v3, v3));
    }
    for (; k < cnt; k++) {
        int2 p = __ldg(&sp[(size_t)k * NN + i]);
        uint4 x = __ldg(&Xin[(size_t)p.x * FBQ + t]);
        float v = __int_as_float(p.y);
        fma8p(acc, x, pack2(v, v));
    }

    float r[8];
#pragma unroll
    for (int q = 0; q < 4; q++) {
        float lo, hi;
        unpack2(acc[q], lo, hi);
        r[2 * q] = alpha * lo;
        r[2 * q + 1] = alpha * hi;
    }
    if (phase) {
        const uint4* Xs = x_buf(xsel);
        uint4 s = __ldg(&Xs[(size_t)i * FBQ + t]);
        const __nv_bfloat162* ps = (const __nv_bfloat162*)&s;
#pragma unroll
        for (int q = 0; q < 4; q++) {
            float2 f = __bfloat1622float2(ps[q]);
            r[2 * q]     -= f.x;
            r[2 * q + 1] -= f.y;
        }
    }
    uint4 o;
    __nv_bfloat162* po = (__nv_bfloat162*)&o;
#pragma unroll
    for (int q = 0; q < 4; q++)
        po[q] = __floats2bfloat162_rn(r[2 * q], r[2 * q + 1]);
    Yout[(size_t)i * FBQ + t] = o;
}

// standalone: phase0 full grid (NN, 2); phase1 chunk grid (nrows, 2)
__global__ __launch_bounds__(264) void spmm0_k(int xsel) {
    spmm_body(blockIdx.y, blockIdx.x, 0, xsel);
}
__global__ __launch_bounds__(264) void spmm1_k(int xsel, int row0) {
    spmm_body(blockIdx.y, row0 + blockIdx.x, 1, xsel);
}

// ---------------- fused1: spmm phase1 chunk (gconv1) + proj1 chunk --------------
// CTAs [0, snrows*2): spmm role. CTAs after: proj1 (n0 = pn0 + blk*64, batch b).
__global__ __launch_bounds__(264) void fused1_k(int pn0, int pnb, int srow0, int snrows,
                                                const float* __restrict__ W,
                                                const float* __restrict__ bias,
                                                const float* __restrict__ hx) {
    __shared__ float As[64][68];
    __shared__ float Ws[66][128];
    int bid = blockIdx.x;
    int sctas = snrows * 2;
    if (bid < sctas) {
        int sup = (bid >= snrows) ? 1 : 0;
        spmm_body(sup, srow0 + bid - sup * snrows, 1, 0);
        return;
    }
    int pbid = bid - sctas;
    int b = pbid / pnb;
    int n0 = pn0 + (pbid - b * pnb) * 64;
    int t = threadIdx.x;
    int tx = t & 15, ty = t >> 4;

    unsigned long long acc[4][4];
#pragma unroll
    for (int rr = 0; rr < 4; rr++)
#pragma unroll
        for (int q = 0; q < 4; q++) acc[rr][q] = 0ULL;

#pragma unroll 1
    for (int m = 0; m < MM; m++) {
        const __nv_bfloat16* Am = (const __nv_bfloat16*)((m == 0) ? g_X0b : g_Mb[m - 1]);
        for (int e = t; e < 64 * FF; e += 264) {
            int r = e / FF, f = e - r * FF;
            As[r][f] = __bfloat162float(Am[(size_t)(n0 + r) * FB + b * FF + f]);
        }
        for (int e = t; e < FF * 128; e += 264) {
            int f = e >> 7, o = e & 127;
            Ws[f][o] = W[(size_t)(f * MM + m) * 128 + o];
        }
        __syncthreads();
        if (t < 256) {
#pragma unroll 6
            for (int kk = 0; kk < FF; kk++) {
                unsigned long long a2[4];
#pragma unroll
                for (int rr = 0; rr < 4; rr++) {
                    float a = As[ty + 16 * rr][kk];
                    a2[rr] = pack2(a, a);
                }
                unsigned long long w2[4];
#pragma unroll
                for (int q = 0; q < 4; q++)
                    w2[q] = *(const unsigned long long*)&Ws[kk][q * 32 + tx * 2];
#pragma unroll
                for (int rr = 0; rr < 4; rr++)
#pragma unroll
                    for (int q = 0; q < 4; q++)
                        ffma2(acc[rr][q], a2[rr], w2[q]);
            }
        }
        __syncthreads();
    }

    if (t < 256) {
        __nv_bfloat16* X2 = (__nv_bfloat16*)g_X2b;
#pragma unroll
        for (int rr = 0; rr < 4; rr++) {
            int n = n0 + ty + 16 * rr;
#pragma unroll
            for (int q = 0; q < 4; q++) {
                float z0, z1;
                unpack2(acc[rr][q], z0, z1);
#pragma unroll
                for (int h = 0; h < 2; h++) {
                    int o = q * 32 + tx * 2 + h;
                    float z = (h == 0 ? z0 : z1) + bias[o];
                    float s = 1.0f / (1.0f + expf(-z));
                    if (o < UU) {
                        float hv = hx[(size_t)b * (NN * UU) + (size_t)n * UU + o];
                        X2[(size_t)n * FB + b * FF + 2 + o] = __float2bfloat16(s * hv);
                    } else {
                        g_U[(size_t)b * (NN * UU) + (size_t)n * UU + (o - UU)] = s;
                    }
                }
            }
        }
    }
}

// ---------------- fused2: spmm phase1 chunk (gconv2) + proj2 chunk --------------
__global__ __launch_bounds__(264) void fused2_k(int pn0, int pnb, int srow0, int snrows,
                                                const float* __restrict__ W2,
                                                const float* __restrict__ b2,
                                                const float* __restrict__ hx,
                                                float* __restrict__ out) {
    __shared__ float As[64][68];
    __shared__ float Ws[66][64];
    int bid = blockIdx.x;
    int sctas = snrows * 2;
    if (bid < sctas) {
        int sup = (bid >= snrows) ? 1 : 0;
        spmm_body(sup, srow0 + bid - sup * snrows, 1, 1);
        return;
    }
    int pbid = bid - sctas;
    int b = pbid / pnb;
    int n0 = pn0 + (pbid - b * pnb) * 64;
    int t = threadIdx.x;
    int tx = t & 15, ty = t >> 4;

    unsigned long long acc[4][2];
#pragma unroll
    for (int rr = 0; rr < 4; rr++)
#pragma unroll
        for (int q = 0; q < 2; q++) acc[rr][q] = 0ULL;

#pragma unroll 1
    for (int m = 0; m < MM; m++) {
        const __nv_bfloat16* Am = (const __nv_bfloat16*)((m == 0) ? g_X2b : g_Mb[m - 1]);
        for (int e = t; e < 64 * FF; e += 264) {
            int r = e / FF, f = e - r * FF;
            As[r][f] = __bfloat162float(Am[(size_t)(n0 + r) * FB + b * FF + f]);
        }
        for (int e = t; e < FF * 64; e += 264) {
            int f = e >> 6, o = e & 63;
            Ws[f][o] = W2[(size_t)(f * MM + m) * 64 + o];
        }
        __syncthreads();
        if (t < 256) {
#pragma unroll 6
            for (int kk = 0; kk < FF; kk++) {
                unsigned long long a2[4];
#pragma unroll
                for (int rr = 0; rr < 4; rr++) {
                    float a = As[ty + 16 * rr][kk];
                    a2[rr] = pack2(a, a);
                }
                unsigned long long w2[2];
#pragma unroll
                for (int q = 0; q < 2; q++)
                    w2[q] = *(const unsigned long long*)&Ws[kk][q * 32 + tx * 2];
#pragma unroll
                for (int rr = 0; rr < 4; rr++)
#pragma unroll
                    for (int q = 0; q < 2; q++)
                        ffma2(acc[rr][q], a2[rr], w2[q]);
            }
        }
        __syncthreads();
    }

    if (t < 256) {
#pragma unroll
        for (int rr = 0; rr < 4; rr++) {
            int n = n0 + ty + 16 * rr;
#pragma unroll
            for (int q = 0; q < 2; q++) {
                float z0, z1;
                unpack2(acc[rr][q], z0, z1);
#pragma unroll
                for (int h = 0; h < 2; h++) {
                    int o = q * 32 + tx * 2 + h;
                    float z = (h == 0 ? z0 : z1) + b2[o];
                    float c = tanhf(z);
                    size_t off = (size_t)b * (NN * UU) + (size_t)n * UU + o;
                    float u = g_U[off];
                    float hv = hx[off];
                    out[off] = u * hv + (1.0f - u) * c;
                }
            }
        }
    }
}

// ---------------- launcher ----------------
extern "C" void kernel_launch(void* const* d_in, const int* in_sizes, int n_in,
                              void* d_out, int out_size) {
    const float* inputs = (const float*)d_in[0];
    const float* hx     = (const float*)d_in[1];
    const float* s0     = (const float*)d_in[2];
    const float* s1     = (const float*)d_in[3];
    const float* W      = (const float*)d_in[4];
    const float* bias   = (const float*)d_in[5];
    const float* W2     = (const float*)d_in[6];
    const float* b2     = (const float*)d_in[7];
    float* out = (float*)d_out;

    build_sparse_k<<<NN / 8, 256>>>(s0, 0);
    build_sparse_k<<<NN / 8, 256>>>(s1, 1);
    build_x_k<<<(NN * FB + 255) / 256, 256>>>(inputs, hx);

    // ---- gconv1 + proj1, pipelined in CH-row chunks ----
    spmm0_k<<<dim3(NN, 2), 264>>>(0);              // M0 = S0@X0, M2 = S1@X0
    spmm1_k<<<dim3(CH, 2), 264>>>(0, 0);           // cheb chunk 0
    for (int c = 1; c < 4; c++)                    // {proj1 chunk c-1 || cheb chunk c}
        fused1_k<<<CH * 2 + BB * PNB, 264>>>((c - 1) * CH, PNB, c * CH, CH, W, bias, hx);
    fused1_k<<<BB * PNB, 264>>>(3 * CH, PNB, 0, 0, W, bias, hx);  // proj1 chunk 3

    // ---- gconv2 + proj2, pipelined ----
    spmm0_k<<<dim3(NN, 2), 264>>>(1);
    spmm1_k<<<dim3(CH, 2), 264>>>(1, 0);
    for (int c = 1; c < 4; c++)
        fused2_k<<<CH * 2 + BB * PNB, 264>>>((c - 1) * CH, PNB, c * CH, CH, W2, b2, hx, out);
    fused2_k<<<BB * PNB, 264>>>(3 * CH, PNB, 0, 0, W2, b2, hx, out);
}